// round 10
// baseline (speedup 1.0000x reference)
#include <cuda_runtime.h>
#include <cuda_bf16.h>
#include <math.h>

#define N_NODES 50000
#define N_EDGES 800000
#define HID 256
#define HEADS 4
#define DH 64
#define NEG 0.2f

#define W0_ELEMS (512 * 256)
#define W1_ELEMS (256 * 256)
#define W2_ELEMS (256 * 256)
#define W_TOTAL (W0_ELEMS + W1_ELEMS + W2_ELEMS)

// ------------------------- device scratch -------------------------
__device__ __nv_bfloat16 g_featb[N_NODES * HID];   // projected features bf16 (gather)
__device__ float g_hA[N_NODES * HID];              // layer-0 output
__device__ float g_hB[N_NODES * HID];              // layer-1 output
__device__ float g_el[N_NODES * HEADS];
__device__ float g_er[N_NODES * HEADS];
__device__ float g_e[(size_t)N_EDGES * HEADS];     // per-edge scores, heads interleaved
__device__ float g_W[W_TOTAL];                     // tf32-rounded TRANSPOSED weights WT[n][k]
__device__ int   g_deg[N_NODES];
__device__ int   g_pos[N_NODES];
__device__ int   g_off[N_NODES + 1];
__device__ int   g_srcs[N_EDGES];

__device__ __forceinline__ unsigned f2tf32(float f) {
    unsigned u;
    asm("cvt.rna.tf32.f32 %0, %1;" : "=r"(u) : "f"(f));
    return u;
}

// ------------------------- weight pre-round + transpose -------------------------
__global__ void wround_kernel(const float* __restrict__ W0,
                              const float* __restrict__ W1,
                              const float* __restrict__ W2) {
    int i = blockIdx.x * blockDim.x + threadIdx.x;
    if (i < W0_ELEMS) {
        int n = i >> 9, k = i & 511;
        g_W[i] = __uint_as_float(f2tf32(W0[k * 256 + n]));
    } else if (i < W0_ELEMS + W1_ELEMS) {
        int j = i - W0_ELEMS;
        int n = j >> 8, k = j & 255;
        g_W[i] = __uint_as_float(f2tf32(W1[k * 256 + n]));
    } else if (i < W_TOTAL) {
        int j = i - W0_ELEMS - W1_ELEMS;
        int n = j >> 8, k = j & 255;
        g_W[i] = __uint_as_float(f2tf32(W2[k * 256 + n]));
    }
}

// ------------------------- zeroing -------------------------
__global__ void zero_kernel() {
    int i = blockIdx.x * blockDim.x + threadIdx.x;
    if (i < N_NODES) { g_deg[i] = 0; g_pos[i] = 0; }
    if (i < N_NODES * HEADS) { g_el[i] = 0.f; g_er[i] = 0.f; }
}

__global__ void zero_elr_kernel() {
    int i = blockIdx.x * blockDim.x + threadIdx.x;
    if (i < N_NODES * HEADS) { g_el[i] = 0.f; g_er[i] = 0.f; }
}

// ------------------------- CSR build -------------------------
__global__ void hist_kernel(const int* __restrict__ dst) {
    int i = blockIdx.x * blockDim.x + threadIdx.x;
    if (i < N_EDGES) atomicAdd(&g_deg[dst[i]], 1);
}

__global__ void scan_offsets_kernel() {
    __shared__ int sums[1024];
    const int SEG = (N_NODES + 1023) / 1024;
    int t = threadIdx.x;
    int b0 = t * SEG;
    int s = 0;
    for (int i = 0; i < SEG; i++) {
        int idx = b0 + i;
        if (idx < N_NODES) s += g_deg[idx];
    }
    sums[t] = s;
    __syncthreads();
    for (int o = 1; o < 1024; o <<= 1) {
        int v = (t >= o) ? sums[t - o] : 0;
        __syncthreads();
        sums[t] += v;
        __syncthreads();
    }
    int run = sums[t] - s;
    for (int i = 0; i < SEG; i++) {
        int idx = b0 + i;
        if (idx < N_NODES) { g_off[idx] = run; run += g_deg[idx]; }
    }
    if (t == 1023) g_off[N_NODES] = sums[1023];
}

__global__ void scatter_kernel(const int* __restrict__ src, const int* __restrict__ dst) {
    int i = blockIdx.x * blockDim.x + threadIdx.x;
    if (i < N_EDGES) {
        int d = dst[i];
        int p = atomicAdd(&g_pos[d], 1);
        g_srcs[g_off[d] + p] = src[i];
    }
}

// ------------------------- TF32 tensor-core GEMM + fused el/er -------------------
// C[M,256] = A[M,K] @ WT^T. Block tile 128x256, BK=32, 512 threads = 16 warps
// (2 x 8), warp tile 64x32 = 4x4 m16n8k8. THREE-stage smem pipeline:
// A: LDG (1-iter lookahead) + tf32 cvt + swizzled STS, frags via ldmatrix.x4.
// B: WT[n][k] via cp.async (2-iter lookahead), frags via ldmatrix.x4.
// Epilogue: bf16 store + fused el/er atomics.
#define BM 128
#define BN 256
#define BK 32
#define NSTAGE 3

__device__ __forceinline__ void mma_tf32(float* c, const unsigned* a, const unsigned* b) {
    asm volatile(
        "mma.sync.aligned.m16n8k8.row.col.f32.tf32.tf32.f32 "
        "{%0,%1,%2,%3}, {%4,%5,%6,%7}, {%8,%9}, {%0,%1,%2,%3};\n"
        : "+f"(c[0]), "+f"(c[1]), "+f"(c[2]), "+f"(c[3])
        : "r"(a[0]), "r"(a[1]), "r"(a[2]), "r"(a[3]), "r"(b[0]), "r"(b[1]));
}

__device__ __forceinline__ void cp16(unsigned smem_dst, const void* gptr) {
    asm volatile("cp.async.cg.shared.global [%0], [%1], 16;\n" :: "r"(smem_dst), "l"(gptr));
}

__device__ __forceinline__ void ldsm4(unsigned& r0, unsigned& r1, unsigned& r2, unsigned& r3,
                                      unsigned addr) {
    asm volatile("ldmatrix.sync.aligned.m8n8.x4.shared.b16 {%0,%1,%2,%3}, [%4];\n"
        : "=r"(r0), "=r"(r1), "=r"(r2), "=r"(r3) : "r"(addr));
}

extern __shared__ unsigned g_smem[];   // A: 3*4096, B: 3*8192 words = 144KB

__global__ __launch_bounds__(512) void gemm_tc_kernel(
    const float* __restrict__ A, const float* __restrict__ WT,
    __nv_bfloat16* __restrict__ Cb,
    const float* __restrict__ alv, const float* __restrict__ arv,
    int M, int K, int HL, int hshift)
{
    unsigned* As = g_smem;                  // NSTAGE * BM*BK
    unsigned AsAddr = (unsigned)__cvta_generic_to_shared(As);
    unsigned BsAddr = AsAddr + NSTAGE * BM * BK * 4;

    int tid = threadIdx.x;
    int lane = tid & 31;
    int w = tid >> 5;
    int wm = w >> 3;          // 0..1  (64 rows each)
    int wn = w & 7;           // 0..7  (32 cols each)
    int rowBase = blockIdx.x * BM;

    float c[4][4][4];
#pragma unroll
    for (int t = 0; t < 4; t++)
#pragma unroll
        for (int u = 0; u < 4; u++)
#pragma unroll
            for (int j = 0; j < 4; j++) c[t][u][j] = 0.f;

    // A staging map: 2 passes of 64 rows
    int am_ld = tid >> 3;            // 0..63
    int ak_ld = (tid & 7) << 2;      // 0,4,...,28
    // B (WT) cp.async map: 4 passes of 64 n-rows, 8 cols of 16B per row
    int bn_ld = tid >> 3;            // 0..63  n-row within pass
    int bc_ld = (tid & 7) << 2;      // k word offset: 0..28

    // ldmatrix lane constants
    int lsw = (lane & 7) << 2;                       // swizzle term
    int amat = lane >> 3;
    int amatoff = (amat >> 1) << 2;                  // 0 or 4
    int arsub = ((amat & 1) << 3) + (lane & 7);      // 0..15
    unsigned arowoff[4];
#pragma unroll
    for (int t = 0; t < 4; t++)
        arowoff[t] = (unsigned)((wm * 64 + t * 16 + arsub) * BK);
    int bh4 = ((lane >> 3) & 1) << 2;                // k sub-group: 0 or 4
    int brsub = ((lane >> 4) << 3) + (lane & 7);     // n-row within 32: 0..15
    unsigned browoff0 = (unsigned)((wn * 32 + brsub) * BK);
    unsigned browoff1 = (unsigned)((wn * 32 + 16 + brsub) * BK);

    float4 ra[2];

#define LOADA(k0)                                                              \
    {                                                                          \
        _Pragma("unroll")                                                      \
        for (int p = 0; p < 2; p++) {                                          \
            int row = rowBase + p * 64 + am_ld;                                \
            ra[p] = (row < M)                                                  \
                ? *(const float4*)(A + (size_t)row * K + (k0) + ak_ld)         \
                : make_float4(0.f, 0.f, 0.f, 0.f);                             \
        }                                                                      \
    }

#define STOREA(buf)                                                            \
    {                                                                          \
        unsigned* Ab = As + (buf) * (BM * BK);                                 \
        _Pragma("unroll")                                                      \
        for (int p = 0; p < 2; p++) {                                          \
            int m = p * 64 + am_ld;                                            \
            int idx = m * BK + (ak_ld ^ ((m & 7) << 2));                       \
            uint4 v;                                                           \
            v.x = f2tf32(ra[p].x); v.y = f2tf32(ra[p].y);                      \
            v.z = f2tf32(ra[p].z); v.w = f2tf32(ra[p].w);                      \
            *(uint4*)&Ab[idx] = v;                                             \
        }                                                                      \
    }

#define CPB(buf, k0)                                                           \
    {                                                                          \
        unsigned base = BsAddr + (buf) * (BK * BN * 4);                        \
        _Pragma("unroll")                                                      \
        for (int p = 0; p < 4; p++) {                                          \
            int n = p * 64 + bn_ld;                                            \
            int idx = n * BK + (bc_ld ^ ((n & 7) << 2));                       \
            cp16(base + idx * 4, WT + (size_t)n * K + (k0) + bc_ld);           \
        }                                                                      \
        asm volatile("cp.async.commit_group;\n");                              \
    }

    int KS = K / BK;   // >= 8 always

    // ---- prologue: stage 0 fully staged; A(1) in regs; B(1) in flight ----
    LOADA(0);
    CPB(0, 0);
    STOREA(0);
    LOADA(BK);
    CPB(1, BK);
    asm volatile("cp.async.wait_group 1;\n");   // B(0) landed
    __syncthreads();

    int s0 = 0, s1 = 1, s2 = 2;
    for (int it = 0; it < KS; ++it) {
        unsigned AbAddr = AsAddr + s0 * (BM * BK * 4);
        unsigned BbAddr = BsAddr + s0 * (BK * BN * 4);

        // stage producers first: A(it+1) store (regs loaded one iter ago),
        // then prefetch A/B for it+2.
        if (it + 1 < KS) STOREA(s1);
        if (it + 2 < KS) {
            LOADA((it + 2) * BK);
            CPB(s2, (it + 2) * BK);
        }

#pragma unroll
        for (int kk = 0; kk < 4; kk++) {
            int kb = kk * 8;
            unsigned af[4][4], bf[4][2];
            unsigned acoff = (unsigned)(((kb | amatoff) ^ lsw) << 2);
            unsigned bcoff = (unsigned)(((kb | bh4) ^ lsw) << 2);
#pragma unroll
            for (int t = 0; t < 4; t++)
                ldsm4(af[t][0], af[t][1], af[t][2], af[t][3],
                      AbAddr + (arowoff[t] << 2) + acoff);
            ldsm4(bf[0][0], bf[0][1], bf[1][0], bf[1][1],
                  BbAddr + (browoff0 << 2) + bcoff);
            ldsm4(bf[2][0], bf[2][1], bf[3][0], bf[3][1],
                  BbAddr + (browoff1 << 2) + bcoff);
#pragma unroll
            for (int t = 0; t < 4; t++)
#pragma unroll
                for (int u = 0; u < 4; u++)
                    mma_tf32(c[t][u], af[t], bf[u]);
        }

        // oldest outstanding B copy (for it+1) must land before next iter.
        if (it + 2 < KS) asm volatile("cp.async.wait_group 1;\n");
        else             asm volatile("cp.async.wait_group 0;\n");
        __syncthreads();

        int tmp = s0; s0 = s1; s1 = s2; s2 = tmp;
    }

    // ---------- epilogue: bf16 store + fused el/er ----------
    float a_c[4][2], r_c[4][2];
#pragma unroll
    for (int u = 0; u < 4; u++) {
        int col = wn * 32 + u * 8 + ((lane & 3) << 1);
        a_c[u][0] = alv[col]; a_c[u][1] = alv[col + 1];
        r_c[u][0] = arv[col]; r_c[u][1] = arv[col + 1];
    }
    int hidx = (wn * 32) >> hshift;   // head for this warp's 32-col window

#pragma unroll
    for (int t = 0; t < 4; t++) {
        int r  = rowBase + wm * 64 + t * 16 + (lane >> 2);
        int r8 = r + 8;
        float peA = 0.f, prA = 0.f, peB = 0.f, prB = 0.f;
#pragma unroll
        for (int u = 0; u < 4; u++) {
            int col = wn * 32 + u * 8 + ((lane & 3) << 1);
            if (r < M) {
                float2 v = make_float2(c[t][u][0], c[t][u][1]);
                *(__nv_bfloat162*)(Cb + (size_t)r * 256 + col) = __float22bfloat162_rn(v);
            }
            if (r8 < M) {
                float2 v = make_float2(c[t][u][2], c[t][u][3]);
                *(__nv_bfloat162*)(Cb + (size_t)r8 * 256 + col) = __float22bfloat162_rn(v);
            }
            peA += c[t][u][0] * a_c[u][0] + c[t][u][1] * a_c[u][1];
            prA += c[t][u][0] * r_c[u][0] + c[t][u][1] * r_c[u][1];
            peB += c[t][u][2] * a_c[u][0] + c[t][u][3] * a_c[u][1];
            prB += c[t][u][2] * r_c[u][0] + c[t][u][3] * r_c[u][1];
        }
#pragma unroll
        for (int o = 1; o < 4; o <<= 1) {
            peA += __shfl_xor_sync(0xffffffffu, peA, o);
            prA += __shfl_xor_sync(0xffffffffu, prA, o);
            peB += __shfl_xor_sync(0xffffffffu, peB, o);
            prB += __shfl_xor_sync(0xffffffffu, prB, o);
        }
        if ((lane & 3) == 0) {
            if (r < M) {
                atomicAdd(&g_el[r * HL + hidx], peA);
                atomicAdd(&g_er[r * HL + hidx], prA);
            }
            if (r8 < M) {
                atomicAdd(&g_el[r8 * HL + hidx], peB);
                atomicAdd(&g_er[r8 * HL + hidx], prB);
            }
        }
    }
#undef LOADA
#undef STOREA
#undef CPB
}

// ------------------------- aggregation (merged heads, bf16 gather) -------------
__global__ __launch_bounds__(256) void agg4_kernel(
    const float* __restrict__ bvec, float* __restrict__ out)
{
    int n = blockIdx.x * 8 + (threadIdx.x >> 5);
    if (n >= N_NODES) return;
    int lane = threadIdx.x & 31;
    int beg = g_off[n], end = g_off[n + 1];
    float4 er4 = *(const float4*)(g_er + 4 * n);

    float4 mx = make_float4(-3.4e38f, -3.4e38f, -3.4e38f, -3.4e38f);
    for (int i = beg + lane; i < end; i += 32) {
        int s = g_srcs[i];
        float4 el4 = *(const float4*)(g_el + 4 * s);
        float4 ev;
        ev.x = el4.x + er4.x; ev.x = (ev.x > 0.f) ? ev.x : ev.x * NEG;
        ev.y = el4.y + er4.y; ev.y = (ev.y > 0.f) ? ev.y : ev.y * NEG;
        ev.z = el4.z + er4.z; ev.z = (ev.z > 0.f) ? ev.z : ev.z * NEG;
        ev.w = el4.w + er4.w; ev.w = (ev.w > 0.f) ? ev.w : ev.w * NEG;
        *(float4*)(g_e + (size_t)4 * i) = ev;
        mx.x = fmaxf(mx.x, ev.x); mx.y = fmaxf(mx.y, ev.y);
        mx.z = fmaxf(mx.z, ev.z); mx.w = fmaxf(mx.w, ev.w);
    }
#pragma unroll
    for (int o = 16; o; o >>= 1) {
        mx.x = fmaxf(mx.x, __shfl_xor_sync(0xffffffffu, mx.x, o));
        mx.y = fmaxf(mx.y, __shfl_xor_sync(0xffffffffu, mx.y, o));
        mx.z = fmaxf(mx.z, __shfl_xor_sync(0xffffffffu, mx.z, o));
        mx.w = fmaxf(mx.w, __shfl_xor_sync(0xffffffffu, mx.w, o));
    }

    float4 se = make_float4(0.f, 0.f, 0.f, 0.f);
    for (int i = beg + lane; i < end; i += 32) {
        float4 ev = *(const float4*)(g_e + (size_t)4 * i);
        ev.x = __expf(ev.x - mx.x); ev.y = __expf(ev.y - mx.y);
        ev.z = __expf(ev.z - mx.z); ev.w = __expf(ev.w - mx.w);
        *(float4*)(g_e + (size_t)4 * i) = ev;
        se.x += ev.x; se.y += ev.y; se.z += ev.z; se.w += ev.w;
    }
#pragma unroll
    for (int o = 16; o; o >>= 1) {
        se.x += __shfl_xor_sync(0xffffffffu, se.x, o);
        se.y += __shfl_xor_sync(0xffffffffu, se.y, o);
        se.z += __shfl_xor_sync(0xffffffffu, se.z, o);
        se.w += __shfl_xor_sync(0xffffffffu, se.w, o);
    }
    int h = lane >> 3;
    float seh = (h == 0) ? se.x : (h == 1) ? se.y : (h == 2) ? se.z : se.w;
    float invh = 1.f / seh;
    __syncwarp();

    float acc[8];
#pragma unroll
    for (int j = 0; j < 8; j++) acc[j] = 0.f;
    for (int i = beg; i < end; i++) {
        int s = g_srcs[i];
        float a = g_e[(size_t)4 * i + h] * invh;
        uint4 v = *(const uint4*)(g_featb + (size_t)s * HID + lane * 8);
        float2 f0 = __bfloat1622float2(*(__nv_bfloat162*)&v.x);
        float2 f1 = __bfloat1622float2(*(__nv_bfloat162*)&v.y);
        float2 f2 = __bfloat1622float2(*(__nv_bfloat162*)&v.z);
        float2 f3 = __bfloat1622float2(*(__nv_bfloat162*)&v.w);
        acc[0] = fmaf(a, f0.x, acc[0]); acc[1] = fmaf(a, f0.y, acc[1]);
        acc[2] = fmaf(a, f1.x, acc[2]); acc[3] = fmaf(a, f1.y, acc[3]);
        acc[4] = fmaf(a, f2.x, acc[4]); acc[5] = fmaf(a, f2.y, acc[5]);
        acc[6] = fmaf(a, f3.x, acc[6]); acc[7] = fmaf(a, f3.y, acc[7]);
    }
#pragma unroll
    for (int j = 0; j < 8; j++) {
        float o = acc[j] + bvec[lane * 8 + j];
        out[(size_t)n * HID + lane * 8 + j] = fmaxf(o, 0.f);
    }
}

// layer 2: single head, D=256, no activation
__global__ __launch_bounds__(256) void agg1_kernel(
    const float* __restrict__ bvec, float* __restrict__ out)
{
    int n = blockIdx.x * 8 + (threadIdx.x >> 5);
    if (n >= N_NODES) return;
    int lane = threadIdx.x & 31;
    int beg = g_off[n], end = g_off[n + 1];
    float ern = g_er[n];

    float mx = -3.4e38f;
    for (int i = beg + lane; i < end; i += 32) {
        float ev = g_el[g_srcs[i]] + ern;
        ev = (ev > 0.f) ? ev : ev * NEG;
        g_e[i] = ev;
        mx = fmaxf(mx, ev);
    }
#pragma unroll
    for (int o = 16; o; o >>= 1) mx = fmaxf(mx, __shfl_xor_sync(0xffffffffu, mx, o));

    float se = 0.f;
    for (int i = beg + lane; i < end; i += 32) {
        float ex = __expf(g_e[i] - mx);
        g_e[i] = ex;
        se += ex;
    }
#pragma unroll
    for (int o = 16; o; o >>= 1) se += __shfl_xor_sync(0xffffffffu, se, o);
    float inv = 1.f / se;
    __syncwarp();

    float acc[8];
#pragma unroll
    for (int j = 0; j < 8; j++) acc[j] = 0.f;
    for (int i = beg; i < end; i++) {
        int s = g_srcs[i];
        float a = g_e[i] * inv;
        uint4 v = *(const uint4*)(g_featb + (size_t)s * HID + lane * 8);
        float2 f0 = __bfloat1622float2(*(__nv_bfloat162*)&v.x);
        float2 f1 = __bfloat1622float2(*(__nv_bfloat162*)&v.y);
        float2 f2 = __bfloat1622float2(*(__nv_bfloat162*)&v.z);
        float2 f3 = __bfloat1622float2(*(__nv_bfloat162*)&v.w);
        acc[0] = fmaf(a, f0.x, acc[0]); acc[1] = fmaf(a, f0.y, acc[1]);
        acc[2] = fmaf(a, f1.x, acc[2]); acc[3] = fmaf(a, f1.y, acc[3]);
        acc[4] = fmaf(a, f2.x, acc[4]); acc[5] = fmaf(a, f2.y, acc[5]);
        acc[6] = fmaf(a, f3.x, acc[6]); acc[7] = fmaf(a, f3.y, acc[7]);
    }
#pragma unroll
    for (int j = 0; j < 8; j++)
        out[(size_t)n * HID + lane * 8 + j] = acc[j] + bvec[lane * 8 + j];
}

// ------------------------- host launch -------------------------
extern "C" void kernel_launch(void* const* d_in, const int* in_sizes, int n_in,
                              void* d_out, int out_size)
{
    const float* feats = (const float*)d_in[0];
    const int*   src   = (const int*)d_in[1];
    const int*   dst   = (const int*)d_in[2];
    const float* W0  = (const float*)d_in[3];
    const float* al0 = (const float*)d_in[4];
    const float* ar0 = (const float*)d_in[5];
    const float* b0  = (const float*)d_in[6];
    const float* W1  = (const float*)d_in[7];
    const float* al1 = (const float*)d_in[8];
    const float* ar1 = (const float*)d_in[9];
    const float* b1  = (const float*)d_in[10];
    const float* W2  = (const float*)d_in[11];
    const float* al2 = (const float*)d_in[12];
    const float* ar2 = (const float*)d_in[13];
    const float* b2  = (const float*)d_in[14];
    float* out = (float*)d_out;

    float *p_hA, *p_hB, *p_W;
    __nv_bfloat16* p_featb;
    cudaGetSymbolAddress((void**)&p_featb, g_featb);
    cudaGetSymbolAddress((void**)&p_hA, g_hA);
    cudaGetSymbolAddress((void**)&p_hB, g_hB);
    cudaGetSymbolAddress((void**)&p_W, g_W);

    const int SMEM_BYTES = NSTAGE * (BM * BK + BK * BN) * 4;   // 144 KB
    cudaFuncSetAttribute(gemm_tc_kernel,
                         cudaFuncAttributeMaxDynamicSharedMemorySize, SMEM_BYTES);

    int ggrid = (N_NODES + BM - 1) / BM;   // 391 full-width tiles
    int nwN = (N_NODES + 7) / 8;
    int nzero = (N_NODES * HEADS + 255) / 256;

    // gemm0 at launch index 3 (fixed ncu capture slot).
    wround_kernel<<<(W_TOTAL + 255) / 256, 256>>>(W0, W1, W2);        // 0
    zero_kernel<<<nzero, 256>>>();                                    // 1 (deg/pos + elr)
    hist_kernel<<<(N_EDGES + 255) / 256, 256>>>(dst);                 // 2
    gemm_tc_kernel<<<ggrid, 512, SMEM_BYTES>>>(feats, p_W, p_featb, al0, ar0, N_NODES, 512, 4, 6);  // 3
    scan_offsets_kernel<<<1, 1024>>>();                               // 4
    scatter_kernel<<<(N_EDGES + 255) / 256, 256>>>(src, dst);         // 5
    agg4_kernel<<<nwN, 256>>>(b0, p_hA);                              // 6

    // layer 1
    zero_elr_kernel<<<nzero, 256>>>();
    gemm_tc_kernel<<<ggrid, 512, SMEM_BYTES>>>(p_hA, p_W + W0_ELEMS, p_featb, al1, ar1, N_NODES, 256, 4, 6);
    agg4_kernel<<<nwN, 256>>>(b1, p_hB);

    // layer 2 (single head spanning all 256 cols: HL=1, hshift=8)
    zero_elr_kernel<<<nzero, 256>>>();
    gemm_tc_kernel<<<ggrid, 512, SMEM_BYTES>>>(p_hB, p_W + W0_ELEMS + W1_ELEMS, p_featb, al2, ar2, N_NODES, 256, 1, 8);
    agg1_kernel<<<nwN, 256>>>(b2, out);
}

// round 12
// speedup vs baseline: 1.0293x; 1.0293x over previous
#include <cuda_runtime.h>
#include <cuda_bf16.h>
#include <math.h>

#define N_NODES 50000
#define N_EDGES 800000
#define HID 256
#define HEADS 4
#define DH 64
#define NEG 0.2f

#define W0_ELEMS (512 * 256)
#define W1_ELEMS (256 * 256)
#define W2_ELEMS (256 * 256)
#define W_TOTAL (W0_ELEMS + W1_ELEMS + W2_ELEMS)
#define ELR_STRIDE (N_NODES * HEADS)

// ------------------------- device scratch -------------------------
__device__ __nv_bfloat16 g_featb[N_NODES * HID];   // projected features bf16 (gather)
__device__ float g_hA[N_NODES * HID];              // layer-0 output
__device__ float g_hB[N_NODES * HID];              // layer-1 output
__device__ float g_el[3 * ELR_STRIDE];             // per-layer el buffers
__device__ float g_er[3 * ELR_STRIDE];             // per-layer er buffers
__device__ float g_e[(size_t)N_EDGES * HEADS];     // per-edge exp-scores, heads interleaved
__device__ float g_W[W_TOTAL];                     // tf32-rounded TRANSPOSED weights WT[n][k]
__device__ int   g_deg[N_NODES];
__device__ int   g_pos[N_NODES];
__device__ int   g_off[N_NODES + 1];
__device__ int   g_srcs[N_EDGES];

__device__ __forceinline__ unsigned f2tf32(float f) {
    unsigned u;
    asm("cvt.rna.tf32.f32 %0, %1;" : "=r"(u) : "f"(f));
    return u;
}

// ------------------------- weight pre-round + transpose -------------------------
__global__ void wround_kernel(const float* __restrict__ W0,
                              const float* __restrict__ W1,
                              const float* __restrict__ W2) {
    int i = blockIdx.x * blockDim.x + threadIdx.x;
    if (i < W0_ELEMS) {
        int n = i >> 9, k = i & 511;
        g_W[i] = __uint_as_float(f2tf32(W0[k * 256 + n]));
    } else if (i < W0_ELEMS + W1_ELEMS) {
        int j = i - W0_ELEMS;
        int n = j >> 8, k = j & 255;
        g_W[i] = __uint_as_float(f2tf32(W1[k * 256 + n]));
    } else if (i < W_TOTAL) {
        int j = i - W0_ELEMS - W1_ELEMS;
        int n = j >> 8, k = j & 255;
        g_W[i] = __uint_as_float(f2tf32(W2[k * 256 + n]));
    }
}

// ------------------------- zeroing (deg/pos + all 3 el/er buffers) ------------
__global__ void zero_kernel() {
    int i = blockIdx.x * blockDim.x + threadIdx.x;
    if (i < N_NODES) { g_deg[i] = 0; g_pos[i] = 0; }
    if (i < 3 * ELR_STRIDE) { g_el[i] = 0.f; g_er[i] = 0.f; }
}

// ------------------------- CSR build -------------------------
__global__ void hist_kernel(const int* __restrict__ dst) {
    int i = blockIdx.x * blockDim.x + threadIdx.x;
    if (i < N_EDGES) atomicAdd(&g_deg[dst[i]], 1);
}

__global__ void scan_offsets_kernel() {
    __shared__ int sums[1024];
    const int SEG = (N_NODES + 1023) / 1024;
    int t = threadIdx.x;
    int b0 = t * SEG;
    int s = 0;
    for (int i = 0; i < SEG; i++) {
        int idx = b0 + i;
        if (idx < N_NODES) s += g_deg[idx];
    }
    sums[t] = s;
    __syncthreads();
    for (int o = 1; o < 1024; o <<= 1) {
        int v = (t >= o) ? sums[t - o] : 0;
        __syncthreads();
        sums[t] += v;
        __syncthreads();
    }
    int run = sums[t] - s;
    for (int i = 0; i < SEG; i++) {
        int idx = b0 + i;
        if (idx < N_NODES) { g_off[idx] = run; run += g_deg[idx]; }
    }
    if (t == 1023) g_off[N_NODES] = sums[1023];
}

__global__ void scatter_kernel(const int* __restrict__ src, const int* __restrict__ dst) {
    int i = blockIdx.x * blockDim.x + threadIdx.x;
    if (i < N_EDGES) {
        int d = dst[i];
        int p = atomicAdd(&g_pos[d], 1);
        g_srcs[g_off[d] + p] = src[i];
    }
}

// ------------------------- TF32 tensor-core GEMM + fused el/er -------------------
// C[M,256] = A[M,K] @ WT^T. Block tile 128x256, BK=32, 512 threads = 16 warps
// (2 x 8), warp tile 64x32 = 4x4 m16n8k8. Two-stage smem pipeline.
// A: LDG + tf32 cvt + swizzled STS, frags via ldmatrix.x4 (b16-pair trick).
// B: WT[n][k] via cp.async, frags via ldmatrix.x4 (2 per kk).
// Epilogue: bf16 store + fused el/er atomics into per-layer buffers.
#define BM 128
#define BN 256
#define BK 32

__device__ __forceinline__ void mma_tf32(float* c, const unsigned* a, const unsigned* b) {
    asm volatile(
        "mma.sync.aligned.m16n8k8.row.col.f32.tf32.tf32.f32 "
        "{%0,%1,%2,%3}, {%4,%5,%6,%7}, {%8,%9}, {%0,%1,%2,%3};\n"
        : "+f"(c[0]), "+f"(c[1]), "+f"(c[2]), "+f"(c[3])
        : "r"(a[0]), "r"(a[1]), "r"(a[2]), "r"(a[3]), "r"(b[0]), "r"(b[1]));
}

__device__ __forceinline__ void cp16(unsigned smem_dst, const void* gptr) {
    asm volatile("cp.async.cg.shared.global [%0], [%1], 16;\n" :: "r"(smem_dst), "l"(gptr));
}

__device__ __forceinline__ void ldsm4(unsigned& r0, unsigned& r1, unsigned& r2, unsigned& r3,
                                      unsigned addr) {
    asm volatile("ldmatrix.sync.aligned.m8n8.x4.shared.b16 {%0,%1,%2,%3}, [%4];\n"
        : "=r"(r0), "=r"(r1), "=r"(r2), "=r"(r3) : "r"(addr));
}

extern __shared__ unsigned g_smem[];   // A: 2*4096, B: 2*8192 words = 96KB

__global__ __launch_bounds__(512) void gemm_tc_kernel(
    const float* __restrict__ A, const float* __restrict__ WT,
    __nv_bfloat16* __restrict__ Cb,
    const float* __restrict__ alv, const float* __restrict__ arv,
    float* __restrict__ elp, float* __restrict__ erp,
    int M, int K, int HL, int hshift)
{
    unsigned* As = g_smem;                  // 2 * BM*BK
    unsigned AsAddr = (unsigned)__cvta_generic_to_shared(As);
    unsigned BsAddr = AsAddr + 2 * BM * BK * 4;

    int tid = threadIdx.x;
    int lane = tid & 31;
    int w = tid >> 5;
    int wm = w >> 3;          // 0..1  (64 rows each)
    int wn = w & 7;           // 0..7  (32 cols each)
    int rowBase = blockIdx.x * BM;

    float c[4][4][4];
#pragma unroll
    for (int t = 0; t < 4; t++)
#pragma unroll
        for (int u = 0; u < 4; u++)
#pragma unroll
            for (int j = 0; j < 4; j++) c[t][u][j] = 0.f;

    int am_ld = tid >> 3;            // 0..63
    int ak_ld = (tid & 7) << 2;      // 0,4,...,28
    int bn_ld = tid >> 3;            // 0..63  n-row within pass
    int bc_ld = (tid & 7) << 2;      // k word offset: 0..28

    int lsw = (lane & 7) << 2;
    int amat = lane >> 3;
    int amatoff = (amat >> 1) << 2;
    int arsub = ((amat & 1) << 3) + (lane & 7);
    unsigned arowoff[4];
#pragma unroll
    for (int t = 0; t < 4; t++)
        arowoff[t] = (unsigned)((wm * 64 + t * 16 + arsub) * BK);
    int bh4 = ((lane >> 3) & 1) << 2;
    int brsub = ((lane >> 4) << 3) + (lane & 7);
    unsigned browoff0 = (unsigned)((wn * 32 + brsub) * BK);
    unsigned browoff1 = (unsigned)((wn * 32 + 16 + brsub) * BK);

    float4 ra[2];

#define LOADA(k0)                                                              \
    {                                                                          \
        _Pragma("unroll")                                                      \
        for (int p = 0; p < 2; p++) {                                          \
            int row = rowBase + p * 64 + am_ld;                                \
            ra[p] = (row < M)                                                  \
                ? *(const float4*)(A + (size_t)row * K + (k0) + ak_ld)         \
                : make_float4(0.f, 0.f, 0.f, 0.f);                             \
        }                                                                      \
    }

#define STOREA(buf)                                                            \
    {                                                                          \
        unsigned* Ab = As + (buf) * (BM * BK);                                 \
        _Pragma("unroll")                                                      \
        for (int p = 0; p < 2; p++) {                                          \
            int m = p * 64 + am_ld;                                            \
            int idx = m * BK + (ak_ld ^ ((m & 7) << 2));                       \
            uint4 v;                                                           \
            v.x = f2tf32(ra[p].x); v.y = f2tf32(ra[p].y);                      \
            v.z = f2tf32(ra[p].z); v.w = f2tf32(ra[p].w);                      \
            *(uint4*)&Ab[idx] = v;                                             \
        }                                                                      \
    }

#define CPB(buf, k0)                                                           \
    {                                                                          \
        unsigned base = BsAddr + (buf) * (BK * BN * 4);                        \
        _Pragma("unroll")                                                      \
        for (int p = 0; p < 4; p++) {                                          \
            int n = p * 64 + bn_ld;                                            \
            int idx = n * BK + (bc_ld ^ ((n & 7) << 2));                       \
            cp16(base + idx * 4, WT + (size_t)n * K + (k0) + bc_ld);           \
        }                                                                      \
        asm volatile("cp.async.commit_group;\n");                              \
    }

    int KS = K / BK;
    LOADA(0);
    CPB(0, 0);
    STOREA(0);
    asm volatile("cp.async.wait_group 0;\n");
    __syncthreads();

    for (int it = 0; it < KS; ++it) {
        int cur = it & 1;
        unsigned AbAddr = AsAddr + cur * (BM * BK * 4);
        unsigned BbAddr = BsAddr + cur * (BK * BN * 4);
        if (it + 1 < KS) {
            LOADA((it + 1) * BK);
            CPB(cur ^ 1, (it + 1) * BK);
        }

#pragma unroll
        for (int kk = 0; kk < 4; kk++) {
            int kb = kk * 8;
            unsigned af[4][4], bf[4][2];
            unsigned acoff = (unsigned)(((kb | amatoff) ^ lsw) << 2);
            unsigned bcoff = (unsigned)(((kb | bh4) ^ lsw) << 2);
#pragma unroll
            for (int t = 0; t < 4; t++)
                ldsm4(af[t][0], af[t][1], af[t][2], af[t][3],
                      AbAddr + (arowoff[t] << 2) + acoff);
            ldsm4(bf[0][0], bf[0][1], bf[1][0], bf[1][1],
                  BbAddr + (browoff0 << 2) + bcoff);
            ldsm4(bf[2][0], bf[2][1], bf[3][0], bf[3][1],
                  BbAddr + (browoff1 << 2) + bcoff);
#pragma unroll
            for (int t = 0; t < 4; t++)
#pragma unroll
                for (int u = 0; u < 4; u++)
                    mma_tf32(c[t][u], af[t], bf[u]);
        }

        if (it + 1 < KS) STOREA(cur ^ 1);
        asm volatile("cp.async.wait_group 0;\n");
        __syncthreads();
    }

    // ---------- epilogue: bf16 store + fused el/er ----------
    float a_c[4][2], r_c[4][2];
#pragma unroll
    for (int u = 0; u < 4; u++) {
        int col = wn * 32 + u * 8 + ((lane & 3) << 1);
        a_c[u][0] = alv[col]; a_c[u][1] = alv[col + 1];
        r_c[u][0] = arv[col]; r_c[u][1] = arv[col + 1];
    }
    int hidx = (wn * 32) >> hshift;

#pragma unroll
    for (int t = 0; t < 4; t++) {
        int r  = rowBase + wm * 64 + t * 16 + (lane >> 2);
        int r8 = r + 8;
        float peA = 0.f, prA = 0.f, peB = 0.f, prB = 0.f;
#pragma unroll
        for (int u = 0; u < 4; u++) {
            int col = wn * 32 + u * 8 + ((lane & 3) << 1);
            if (r < M) {
                float2 v = make_float2(c[t][u][0], c[t][u][1]);
                *(__nv_bfloat162*)(Cb + (size_t)r * 256 + col) = __float22bfloat162_rn(v);
            }
            if (r8 < M) {
                float2 v = make_float2(c[t][u][2], c[t][u][3]);
                *(__nv_bfloat162*)(Cb + (size_t)r8 * 256 + col) = __float22bfloat162_rn(v);
            }
            peA += c[t][u][0] * a_c[u][0] + c[t][u][1] * a_c[u][1];
            prA += c[t][u][0] * r_c[u][0] + c[t][u][1] * r_c[u][1];
            peB += c[t][u][2] * a_c[u][0] + c[t][u][3] * a_c[u][1];
            prB += c[t][u][2] * r_c[u][0] + c[t][u][3] * r_c[u][1];
        }
#pragma unroll
        for (int o = 1; o < 4; o <<= 1) {
            peA += __shfl_xor_sync(0xffffffffu, peA, o);
            prA += __shfl_xor_sync(0xffffffffu, prA, o);
            peB += __shfl_xor_sync(0xffffffffu, peB, o);
            prB += __shfl_xor_sync(0xffffffffu, prB, o);
        }
        if ((lane & 3) == 0) {
            if (r < M) {
                atomicAdd(&elp[r * HL + hidx], peA);
                atomicAdd(&erp[r * HL + hidx], prA);
            }
            if (r8 < M) {
                atomicAdd(&elp[r8 * HL + hidx], peB);
                atomicAdd(&erp[r8 * HL + hidx], prB);
            }
        }
    }
#undef LOADA
#undef STOREA
#undef CPB
}

// ------------------------- aggregation (merged heads, bf16 gather) -------------
// 2-pass: direct exp (scores are O(1); no max subtraction needed), then gather.
__global__ __launch_bounds__(256) void agg4_kernel(
    const float* __restrict__ bvec, float* __restrict__ out,
    const float* __restrict__ elp, const float* __restrict__ erp)
{
    int n = blockIdx.x * 8 + (threadIdx.x >> 5);
    if (n >= N_NODES) return;
    int lane = threadIdx.x & 31;
    int beg = g_off[n], end = g_off[n + 1];
    float4 er4 = *(const float4*)(erp + 4 * n);

    // pass 1: exp-scores + sum
    float4 se = make_float4(0.f, 0.f, 0.f, 0.f);
    for (int i = beg + lane; i < end; i += 32) {
        int s = g_srcs[i];
        float4 el4 = *(const float4*)(elp + 4 * s);
        float4 ev;
        ev.x = el4.x + er4.x; ev.x = (ev.x > 0.f) ? ev.x : ev.x * NEG; ev.x = __expf(ev.x);
        ev.y = el4.y + er4.y; ev.y = (ev.y > 0.f) ? ev.y : ev.y * NEG; ev.y = __expf(ev.y);
        ev.z = el4.z + er4.z; ev.z = (ev.z > 0.f) ? ev.z : ev.z * NEG; ev.z = __expf(ev.z);
        ev.w = el4.w + er4.w; ev.w = (ev.w > 0.f) ? ev.w : ev.w * NEG; ev.w = __expf(ev.w);
        *(float4*)(g_e + (size_t)4 * i) = ev;
        se.x += ev.x; se.y += ev.y; se.z += ev.z; se.w += ev.w;
    }
#pragma unroll
    for (int o = 16; o; o >>= 1) {
        se.x += __shfl_xor_sync(0xffffffffu, se.x, o);
        se.y += __shfl_xor_sync(0xffffffffu, se.y, o);
        se.z += __shfl_xor_sync(0xffffffffu, se.z, o);
        se.w += __shfl_xor_sync(0xffffffffu, se.w, o);
    }
    int h = lane >> 3;
    float seh = (h == 0) ? se.x : (h == 1) ? se.y : (h == 2) ? se.z : se.w;
    float invh = 1.f / seh;
    __syncwarp();

    // pass 2: weighted feature gather (unrolled x2 for MLP)
    float acc[8];
#pragma unroll
    for (int j = 0; j < 8; j++) acc[j] = 0.f;
    int i = beg;
    for (; i + 1 < end; i += 2) {
        int s0 = g_srcs[i], s1 = g_srcs[i + 1];
        float a0 = g_e[(size_t)4 * i + h] * invh;
        float a1 = g_e[(size_t)4 * (i + 1) + h] * invh;
        uint4 v0 = *(const uint4*)(g_featb + (size_t)s0 * HID + lane * 8);
        uint4 v1 = *(const uint4*)(g_featb + (size_t)s1 * HID + lane * 8);
        float2 p;
        p = __bfloat1622float2(*(__nv_bfloat162*)&v0.x); acc[0] = fmaf(a0, p.x, acc[0]); acc[1] = fmaf(a0, p.y, acc[1]);
        p = __bfloat1622float2(*(__nv_bfloat162*)&v0.y); acc[2] = fmaf(a0, p.x, acc[2]); acc[3] = fmaf(a0, p.y, acc[3]);
        p = __bfloat1622float2(*(__nv_bfloat162*)&v0.z); acc[4] = fmaf(a0, p.x, acc[4]); acc[5] = fmaf(a0, p.y, acc[5]);
        p = __bfloat1622float2(*(__nv_bfloat162*)&v0.w); acc[6] = fmaf(a0, p.x, acc[6]); acc[7] = fmaf(a0, p.y, acc[7]);
        p = __bfloat1622float2(*(__nv_bfloat162*)&v1.x); acc[0] = fmaf(a1, p.x, acc[0]); acc[1] = fmaf(a1, p.y, acc[1]);
        p = __bfloat1622float2(*(__nv_bfloat162*)&v1.y); acc[2] = fmaf(a1, p.x, acc[2]); acc[3] = fmaf(a1, p.y, acc[3]);
        p = __bfloat1622float2(*(__nv_bfloat162*)&v1.z); acc[4] = fmaf(a1, p.x, acc[4]); acc[5] = fmaf(a1, p.y, acc[5]);
        p = __bfloat1622float2(*(__nv_bfloat162*)&v1.w); acc[6] = fmaf(a1, p.x, acc[6]); acc[7] = fmaf(a1, p.y, acc[7]);
    }
    if (i < end) {
        int s0 = g_srcs[i];
        float a0 = g_e[(size_t)4 * i + h] * invh;
        uint4 v0 = *(const uint4*)(g_featb + (size_t)s0 * HID + lane * 8);
        float2 p;
        p = __bfloat1622float2(*(__nv_bfloat162*)&v0.x); acc[0] = fmaf(a0, p.x, acc[0]); acc[1] = fmaf(a0, p.y, acc[1]);
        p = __bfloat1622float2(*(__nv_bfloat162*)&v0.y); acc[2] = fmaf(a0, p.x, acc[2]); acc[3] = fmaf(a0, p.y, acc[3]);
        p = __bfloat1622float2(*(__nv_bfloat162*)&v0.z); acc[4] = fmaf(a0, p.x, acc[4]); acc[5] = fmaf(a0, p.y, acc[5]);
        p = __bfloat1622float2(*(__nv_bfloat162*)&v0.w); acc[6] = fmaf(a0, p.x, acc[6]); acc[7] = fmaf(a0, p.y, acc[7]);
    }
#pragma unroll
    for (int j = 0; j < 8; j++) {
        float o = acc[j] + bvec[lane * 8 + j];
        out[(size_t)n * HID + lane * 8 + j] = fmaxf(o, 0.f);
    }
}

// layer 2: single head, D=256, no activation; same 2-pass structure
__global__ __launch_bounds__(256) void agg1_kernel(
    const float* __restrict__ bvec, float* __restrict__ out,
    const float* __restrict__ elp, const float* __restrict__ erp)
{
    int n = blockIdx.x * 8 + (threadIdx.x >> 5);
    if (n >= N_NODES) return;
    int lane = threadIdx.x & 31;
    int beg = g_off[n], end = g_off[n + 1];
    float ern = erp[n];

    float se = 0.f;
    for (int i = beg + lane; i < end; i += 32) {
        float ev = elp[g_srcs[i]] + ern;
        ev = (ev > 0.f) ? ev : ev * NEG;
        ev = __expf(ev);
        g_e[i] = ev;
        se += ev;
    }
#pragma unroll
    for (int o = 16; o; o >>= 1) se += __shfl_xor_sync(0xffffffffu, se, o);
    float inv = 1.f / se;
    __syncwarp();

    float acc[8];
#pragma unroll
    for (int j = 0; j < 8; j++) acc[j] = 0.f;
    int i = beg;
    for (; i + 1 < end; i += 2) {
        int s0 = g_srcs[i], s1 = g_srcs[i + 1];
        float a0 = g_e[i] * inv, a1 = g_e[i + 1] * inv;
        uint4 v0 = *(const uint4*)(g_featb + (size_t)s0 * HID + lane * 8);
        uint4 v1 = *(const uint4*)(g_featb + (size_t)s1 * HID + lane * 8);
        float2 p;
        p = __bfloat1622float2(*(__nv_bfloat162*)&v0.x); acc[0] = fmaf(a0, p.x, acc[0]); acc[1] = fmaf(a0, p.y, acc[1]);
        p = __bfloat1622float2(*(__nv_bfloat162*)&v0.y); acc[2] = fmaf(a0, p.x, acc[2]); acc[3] = fmaf(a0, p.y, acc[3]);
        p = __bfloat1622float2(*(__nv_bfloat162*)&v0.z); acc[4] = fmaf(a0, p.x, acc[4]); acc[5] = fmaf(a0, p.y, acc[5]);
        p = __bfloat1622float2(*(__nv_bfloat162*)&v0.w); acc[6] = fmaf(a0, p.x, acc[6]); acc[7] = fmaf(a0, p.y, acc[7]);
        p = __bfloat1622float2(*(__nv_bfloat162*)&v1.x); acc[0] = fmaf(a1, p.x, acc[0]); acc[1] = fmaf(a1, p.y, acc[1]);
        p = __bfloat1622float2(*(__nv_bfloat162*)&v1.y); acc[2] = fmaf(a1, p.x, acc[2]); acc[3] = fmaf(a1, p.y, acc[3]);
        p = __bfloat1622float2(*(__nv_bfloat162*)&v1.z); acc[4] = fmaf(a1, p.x, acc[4]); acc[5] = fmaf(a1, p.y, acc[5]);
        p = __bfloat1622float2(*(__nv_bfloat162*)&v1.w); acc[6] = fmaf(a1, p.x, acc[6]); acc[7] = fmaf(a1, p.y, acc[7]);
    }
    if (i < end) {
        int s0 = g_srcs[i];
        float a0 = g_e[i] * inv;
        uint4 v0 = *(const uint4*)(g_featb + (size_t)s0 * HID + lane * 8);
        float2 p;
        p = __bfloat1622float2(*(__nv_bfloat162*)&v0.x); acc[0] = fmaf(a0, p.x, acc[0]); acc[1] = fmaf(a0, p.y, acc[1]);
        p = __bfloat1622float2(*(__nv_bfloat162*)&v0.y); acc[2] = fmaf(a0, p.x, acc[2]); acc[3] = fmaf(a0, p.y, acc[3]);
        p = __bfloat1622float2(*(__nv_bfloat162*)&v0.z); acc[4] = fmaf(a0, p.x, acc[4]); acc[5] = fmaf(a0, p.y, acc[5]);
        p = __bfloat1622float2(*(__nv_bfloat162*)&v0.w); acc[6] = fmaf(a0, p.x, acc[6]); acc[7] = fmaf(a0, p.y, acc[7]);
    }
#pragma unroll
    for (int j = 0; j < 8; j++)
        out[(size_t)n * HID + lane * 8 + j] = acc[j] + bvec[lane * 8 + j];
}

// ------------------------- host launch -------------------------
extern "C" void kernel_launch(void* const* d_in, const int* in_sizes, int n_in,
                              void* d_out, int out_size)
{
    const float* feats = (const float*)d_in[0];
    const int*   src   = (const int*)d_in[1];
    const int*   dst   = (const int*)d_in[2];
    const float* W0  = (const float*)d_in[3];
    const float* al0 = (const float*)d_in[4];
    const float* ar0 = (const float*)d_in[5];
    const float* b0  = (const float*)d_in[6];
    const float* W1  = (const float*)d_in[7];
    const float* al1 = (const float*)d_in[8];
    const float* ar1 = (const float*)d_in[9];
    const float* b1  = (const float*)d_in[10];
    const float* W2  = (const float*)d_in[11];
    const float* al2 = (const float*)d_in[12];
    const float* ar2 = (const float*)d_in[13];
    const float* b2  = (const float*)d_in[14];
    float* out = (float*)d_out;

    float *p_hA, *p_hB, *p_W, *p_el, *p_er;
    __nv_bfloat16* p_featb;
    cudaGetSymbolAddress((void**)&p_featb, g_featb);
    cudaGetSymbolAddress((void**)&p_hA, g_hA);
    cudaGetSymbolAddress((void**)&p_hB, g_hB);
    cudaGetSymbolAddress((void**)&p_W, g_W);
    cudaGetSymbolAddress((void**)&p_el, g_el);
    cudaGetSymbolAddress((void**)&p_er, g_er);

    const int SMEM_BYTES = 2 * (BM * BK + BK * BN) * 4;   // 96 KB
    cudaFuncSetAttribute(gemm_tc_kernel,
                         cudaFuncAttributeMaxDynamicSharedMemorySize, SMEM_BYTES);

    int ggrid = (N_NODES + BM - 1) / BM;   // 391 full-width tiles
    int nwN = (N_NODES + 7) / 8;
    int nzero = (3 * ELR_STRIDE + 255) / 256;

    float* el0 = p_el;                  float* er0 = p_er;
    float* el1 = p_el + ELR_STRIDE;     float* er1 = p_er + ELR_STRIDE;
    float* el2 = p_el + 2 * ELR_STRIDE; float* er2 = p_er + 2 * ELR_STRIDE;

    // gemm0 at launch index 3 (fixed ncu capture slot).
    wround_kernel<<<(W_TOTAL + 255) / 256, 256>>>(W0, W1, W2);        // 0
    zero_kernel<<<nzero, 256>>>();                                    // 1
    hist_kernel<<<(N_EDGES + 255) / 256, 256>>>(dst);                 // 2
    gemm_tc_kernel<<<ggrid, 512, SMEM_BYTES>>>(feats, p_W, p_featb, al0, ar0, el0, er0, N_NODES, 512, 4, 6);  // 3
    scan_offsets_kernel<<<1, 1024>>>();                               // 4
    scatter_kernel<<<(N_EDGES + 255) / 256, 256>>>(src, dst);         // 5
    agg4_kernel<<<nwN, 256>>>(b0, p_hA, el0, er0);                    // 6

    // layer 1
    gemm_tc_kernel<<<ggrid, 512, SMEM_BYTES>>>(p_hA, p_W + W0_ELEMS, p_featb, al1, ar1, el1, er1, N_NODES, 256, 4, 6);
    agg4_kernel<<<nwN, 256>>>(b1, p_hB, el1, er1);

    // layer 2 (single head spanning all 256 cols: HL=1, hshift=8)
    gemm_tc_kernel<<<ggrid, 512, SMEM_BYTES>>>(p_hB, p_W + W0_ELEMS + W1_ELEMS, p_featb, al2, ar2, el2, er2, N_NODES, 256, 1, 8);
    agg1_kernel<<<nwN, 256>>>(b2, out, el2, er2);
}

// round 13
// speedup vs baseline: 1.0984x; 1.0671x over previous
#include <cuda_runtime.h>
#include <cuda_bf16.h>
#include <math.h>

#define N_NODES 50000
#define N_EDGES 800000
#define HID 256
#define HEADS 4
#define DH 64
#define NEG 0.2f

#define W0_ELEMS (512 * 256)
#define W1_ELEMS (256 * 256)
#define W2_ELEMS (256 * 256)
#define W_TOTAL (W0_ELEMS + W1_ELEMS + W2_ELEMS)
#define ELR_STRIDE (N_NODES * HEADS)

// ------------------------- device scratch -------------------------
__device__ __nv_bfloat16 g_featb[N_NODES * HID];   // projected features bf16 (gather)
__device__ float g_hA[N_NODES * HID];              // layer-0 output
__device__ float g_hB[N_NODES * HID];              // layer-1 output
__device__ float g_el[3 * ELR_STRIDE];             // per-layer el buffers
__device__ float g_er[3 * ELR_STRIDE];             // per-layer er buffers
__device__ float g_e[(size_t)N_EDGES * HEADS];     // per-edge exp-scores, heads interleaved
__device__ float g_W[W_TOTAL];                     // tf32-rounded TRANSPOSED weights WT[n][k]
__device__ int   g_deg[N_NODES];
__device__ int   g_pos[N_NODES];
__device__ int   g_off[N_NODES + 1];
__device__ int   g_srcs[N_EDGES];

__device__ __forceinline__ unsigned f2tf32(float f) {
    unsigned u;
    asm("cvt.rna.tf32.f32 %0, %1;" : "=r"(u) : "f"(f));
    return u;
}

// ------------------------- weight pre-round + transpose -------------------------
__global__ void wround_kernel(const float* __restrict__ W0,
                              const float* __restrict__ W1,
                              const float* __restrict__ W2) {
    int i = blockIdx.x * blockDim.x + threadIdx.x;
    if (i < W0_ELEMS) {
        int n = i >> 9, k = i & 511;
        g_W[i] = __uint_as_float(f2tf32(W0[k * 256 + n]));
    } else if (i < W0_ELEMS + W1_ELEMS) {
        int j = i - W0_ELEMS;
        int n = j >> 8, k = j & 255;
        g_W[i] = __uint_as_float(f2tf32(W1[k * 256 + n]));
    } else if (i < W_TOTAL) {
        int j = i - W0_ELEMS - W1_ELEMS;
        int n = j >> 8, k = j & 255;
        g_W[i] = __uint_as_float(f2tf32(W2[k * 256 + n]));
    }
}

// ------------------------- zeroing (split across streams) -------------------------
__global__ void zero_elr_kernel() {
    int i = blockIdx.x * blockDim.x + threadIdx.x;
    if (i < 3 * ELR_STRIDE) { g_el[i] = 0.f; g_er[i] = 0.f; }
}

__global__ void zero_deg_kernel() {
    int i = blockIdx.x * blockDim.x + threadIdx.x;
    if (i < N_NODES) { g_deg[i] = 0; g_pos[i] = 0; }
}

// ------------------------- CSR build -------------------------
__global__ void hist_kernel(const int* __restrict__ dst) {
    int i = blockIdx.x * blockDim.x + threadIdx.x;
    if (i < N_EDGES) atomicAdd(&g_deg[dst[i]], 1);
}

__global__ void scan_offsets_kernel() {
    __shared__ int sums[1024];
    const int SEG = (N_NODES + 1023) / 1024;
    int t = threadIdx.x;
    int b0 = t * SEG;
    int s = 0;
    for (int i = 0; i < SEG; i++) {
        int idx = b0 + i;
        if (idx < N_NODES) s += g_deg[idx];
    }
    sums[t] = s;
    __syncthreads();
    for (int o = 1; o < 1024; o <<= 1) {
        int v = (t >= o) ? sums[t - o] : 0;
        __syncthreads();
        sums[t] += v;
        __syncthreads();
    }
    int run = sums[t] - s;
    for (int i = 0; i < SEG; i++) {
        int idx = b0 + i;
        if (idx < N_NODES) { g_off[idx] = run; run += g_deg[idx]; }
    }
    if (t == 1023) g_off[N_NODES] = sums[1023];
}

__global__ void scatter_kernel(const int* __restrict__ src, const int* __restrict__ dst) {
    int i = blockIdx.x * blockDim.x + threadIdx.x;
    if (i < N_EDGES) {
        int d = dst[i];
        int p = atomicAdd(&g_pos[d], 1);
        g_srcs[g_off[d] + p] = src[i];
    }
}

// ------------------------- TF32 tensor-core GEMM + fused el/er -------------------
#define BM 128
#define BN 256
#define BK 32

__device__ __forceinline__ void mma_tf32(float* c, const unsigned* a, const unsigned* b) {
    asm volatile(
        "mma.sync.aligned.m16n8k8.row.col.f32.tf32.tf32.f32 "
        "{%0,%1,%2,%3}, {%4,%5,%6,%7}, {%8,%9}, {%0,%1,%2,%3};\n"
        : "+f"(c[0]), "+f"(c[1]), "+f"(c[2]), "+f"(c[3])
        : "r"(a[0]), "r"(a[1]), "r"(a[2]), "r"(a[3]), "r"(b[0]), "r"(b[1]));
}

__device__ __forceinline__ void cp16(unsigned smem_dst, const void* gptr) {
    asm volatile("cp.async.cg.shared.global [%0], [%1], 16;\n" :: "r"(smem_dst), "l"(gptr));
}

__device__ __forceinline__ void ldsm4(unsigned& r0, unsigned& r1, unsigned& r2, unsigned& r3,
                                      unsigned addr) {
    asm volatile("ldmatrix.sync.aligned.m8n8.x4.shared.b16 {%0,%1,%2,%3}, [%4];\n"
        : "=r"(r0), "=r"(r1), "=r"(r2), "=r"(r3) : "r"(addr));
}

extern __shared__ unsigned g_smem[];   // A: 2*4096, B: 2*8192 words = 96KB

__global__ __launch_bounds__(512) void gemm_tc_kernel(
    const float* __restrict__ A, const float* __restrict__ WT,
    __nv_bfloat16* __restrict__ Cb,
    const float* __restrict__ alv, const float* __restrict__ arv,
    float* __restrict__ elp, float* __restrict__ erp,
    int M, int K, int HL, int hshift)
{
    unsigned* As = g_smem;                  // 2 * BM*BK
    unsigned AsAddr = (unsigned)__cvta_generic_to_shared(As);
    unsigned BsAddr = AsAddr + 2 * BM * BK * 4;

    int tid = threadIdx.x;
    int lane = tid & 31;
    int w = tid >> 5;
    int wm = w >> 3;          // 0..1  (64 rows each)
    int wn = w & 7;           // 0..7  (32 cols each)
    int rowBase = blockIdx.x * BM;

    float c[4][4][4];
#pragma unroll
    for (int t = 0; t < 4; t++)
#pragma unroll
        for (int u = 0; u < 4; u++)
#pragma unroll
            for (int j = 0; j < 4; j++) c[t][u][j] = 0.f;

    int am_ld = tid >> 3;            // 0..63
    int ak_ld = (tid & 7) << 2;      // 0,4,...,28
    int bn_ld = tid >> 3;            // 0..63  n-row within pass
    int bc_ld = (tid & 7) << 2;      // k word offset: 0..28

    int lsw = (lane & 7) << 2;
    int amat = lane >> 3;
    int amatoff = (amat >> 1) << 2;
    int arsub = ((amat & 1) << 3) + (lane & 7);
    unsigned arowoff[4];
#pragma unroll
    for (int t = 0; t < 4; t++)
        arowoff[t] = (unsigned)((wm * 64 + t * 16 + arsub) * BK);
    int bh4 = ((lane >> 3) & 1) << 2;
    int brsub = ((lane >> 4) << 3) + (lane & 7);
    unsigned browoff0 = (unsigned)((wn * 32 + brsub) * BK);
    unsigned browoff1 = (unsigned)((wn * 32 + 16 + brsub) * BK);

    float4 ra[2];

#define LOADA(k0)                                                              \
    {                                                                          \
        _Pragma("unroll")                                                      \
        for (int p = 0; p < 2; p++) {                                          \
            int row = rowBase + p * 64 + am_ld;                                \
            ra[p] = (row < M)                                                  \
                ? *(const float4*)(A + (size_t)row * K + (k0) + ak_ld)         \
                : make_float4(0.f, 0.f, 0.f, 0.f);                             \
        }                                                                      \
    }

#define STOREA(buf)                                                            \
    {                                                                          \
        unsigned* Ab = As + (buf) * (BM * BK);                                 \
        _Pragma("unroll")                                                      \
        for (int p = 0; p < 2; p++) {                                          \
            int m = p * 64 + am_ld;                                            \
            int idx = m * BK + (ak_ld ^ ((m & 7) << 2));                       \
            uint4 v;                                                           \
            v.x = f2tf32(ra[p].x); v.y = f2tf32(ra[p].y);                      \
            v.z = f2tf32(ra[p].z); v.w = f2tf32(ra[p].w);                      \
            *(uint4*)&Ab[idx] = v;                                             \
        }                                                                      \
    }

#define CPB(buf, k0)                                                           \
    {                                                                          \
        unsigned base = BsAddr + (buf) * (BK * BN * 4);                        \
        _Pragma("unroll")                                                      \
        for (int p = 0; p < 4; p++) {                                          \
            int n = p * 64 + bn_ld;                                            \
            int idx = n * BK + (bc_ld ^ ((n & 7) << 2));                       \
            cp16(base + idx * 4, WT + (size_t)n * K + (k0) + bc_ld);           \
        }                                                                      \
        asm volatile("cp.async.commit_group;\n");                              \
    }

    int KS = K / BK;
    LOADA(0);
    CPB(0, 0);
    STOREA(0);
    asm volatile("cp.async.wait_group 0;\n");
    __syncthreads();

    for (int it = 0; it < KS; ++it) {
        int cur = it & 1;
        unsigned AbAddr = AsAddr + cur * (BM * BK * 4);
        unsigned BbAddr = BsAddr + cur * (BK * BN * 4);
        if (it + 1 < KS) {
            LOADA((it + 1) * BK);
            CPB(cur ^ 1, (it + 1) * BK);
        }

#pragma unroll
        for (int kk = 0; kk < 4; kk++) {
            int kb = kk * 8;
            unsigned af[4][4], bf[4][2];
            unsigned acoff = (unsigned)(((kb | amatoff) ^ lsw) << 2);
            unsigned bcoff = (unsigned)(((kb | bh4) ^ lsw) << 2);
#pragma unroll
            for (int t = 0; t < 4; t++)
                ldsm4(af[t][0], af[t][1], af[t][2], af[t][3],
                      AbAddr + (arowoff[t] << 2) + acoff);
            ldsm4(bf[0][0], bf[0][1], bf[1][0], bf[1][1],
                  BbAddr + (browoff0 << 2) + bcoff);
            ldsm4(bf[2][0], bf[2][1], bf[3][0], bf[3][1],
                  BbAddr + (browoff1 << 2) + bcoff);
#pragma unroll
            for (int t = 0; t < 4; t++)
#pragma unroll
                for (int u = 0; u < 4; u++)
                    mma_tf32(c[t][u], af[t], bf[u]);
        }

        if (it + 1 < KS) STOREA(cur ^ 1);
        asm volatile("cp.async.wait_group 0;\n");
        __syncthreads();
    }

    // ---------- epilogue: bf16 store + fused el/er ----------
    float a_c[4][2], r_c[4][2];
#pragma unroll
    for (int u = 0; u < 4; u++) {
        int col = wn * 32 + u * 8 + ((lane & 3) << 1);
        a_c[u][0] = alv[col]; a_c[u][1] = alv[col + 1];
        r_c[u][0] = arv[col]; r_c[u][1] = arv[col + 1];
    }
    int hidx = (wn * 32) >> hshift;

#pragma unroll
    for (int t = 0; t < 4; t++) {
        int r  = rowBase + wm * 64 + t * 16 + (lane >> 2);
        int r8 = r + 8;
        float peA = 0.f, prA = 0.f, peB = 0.f, prB = 0.f;
#pragma unroll
        for (int u = 0; u < 4; u++) {
            int col = wn * 32 + u * 8 + ((lane & 3) << 1);
            if (r < M) {
                float2 v = make_float2(c[t][u][0], c[t][u][1]);
                *(__nv_bfloat162*)(Cb + (size_t)r * 256 + col) = __float22bfloat162_rn(v);
            }
            if (r8 < M) {
                float2 v = make_float2(c[t][u][2], c[t][u][3]);
                *(__nv_bfloat162*)(Cb + (size_t)r8 * 256 + col) = __float22bfloat162_rn(v);
            }
            peA += c[t][u][0] * a_c[u][0] + c[t][u][1] * a_c[u][1];
            prA += c[t][u][0] * r_c[u][0] + c[t][u][1] * r_c[u][1];
            peB += c[t][u][2] * a_c[u][0] + c[t][u][3] * a_c[u][1];
            prB += c[t][u][2] * r_c[u][0] + c[t][u][3] * r_c[u][1];
        }
#pragma unroll
        for (int o = 1; o < 4; o <<= 1) {
            peA += __shfl_xor_sync(0xffffffffu, peA, o);
            prA += __shfl_xor_sync(0xffffffffu, prA, o);
            peB += __shfl_xor_sync(0xffffffffu, peB, o);
            prB += __shfl_xor_sync(0xffffffffu, prB, o);
        }
        if ((lane & 3) == 0) {
            if (r < M) {
                atomicAdd(&elp[r * HL + hidx], peA);
                atomicAdd(&erp[r * HL + hidx], prA);
            }
            if (r8 < M) {
                atomicAdd(&elp[r8 * HL + hidx], peB);
                atomicAdd(&erp[r8 * HL + hidx], prB);
            }
        }
    }
#undef LOADA
#undef STOREA
#undef CPB
}

// ------------------------- aggregation (merged heads, bf16 gather) -------------
__global__ __launch_bounds__(256) void agg4_kernel(
    const float* __restrict__ bvec, float* __restrict__ out,
    const float* __restrict__ elp, const float* __restrict__ erp)
{
    int n = blockIdx.x * 8 + (threadIdx.x >> 5);
    if (n >= N_NODES) return;
    int lane = threadIdx.x & 31;
    int beg = g_off[n], end = g_off[n + 1];
    float4 er4 = *(const float4*)(erp + 4 * n);

    float4 se = make_float4(0.f, 0.f, 0.f, 0.f);
    for (int i = beg + lane; i < end; i += 32) {
        int s = g_srcs[i];
        float4 el4 = *(const float4*)(elp + 4 * s);
        float4 ev;
        ev.x = el4.x + er4.x; ev.x = (ev.x > 0.f) ? ev.x : ev.x * NEG; ev.x = __expf(ev.x);
        ev.y = el4.y + er4.y; ev.y = (ev.y > 0.f) ? ev.y : ev.y * NEG; ev.y = __expf(ev.y);
        ev.z = el4.z + er4.z; ev.z = (ev.z > 0.f) ? ev.z : ev.z * NEG; ev.z = __expf(ev.z);
        ev.w = el4.w + er4.w; ev.w = (ev.w > 0.f) ? ev.w : ev.w * NEG; ev.w = __expf(ev.w);
        *(float4*)(g_e + (size_t)4 * i) = ev;
        se.x += ev.x; se.y += ev.y; se.z += ev.z; se.w += ev.w;
    }
#pragma unroll
    for (int o = 16; o; o >>= 1) {
        se.x += __shfl_xor_sync(0xffffffffu, se.x, o);
        se.y += __shfl_xor_sync(0xffffffffu, se.y, o);
        se.z += __shfl_xor_sync(0xffffffffu, se.z, o);
        se.w += __shfl_xor_sync(0xffffffffu, se.w, o);
    }
    int h = lane >> 3;
    float seh = (h == 0) ? se.x : (h == 1) ? se.y : (h == 2) ? se.z : se.w;
    float invh = 1.f / seh;
    __syncwarp();

    float acc[8];
#pragma unroll
    for (int j = 0; j < 8; j++) acc[j] = 0.f;
    int i = beg;
    for (; i + 1 < end; i += 2) {
        int s0 = g_srcs[i], s1 = g_srcs[i + 1];
        float a0 = g_e[(size_t)4 * i + h] * invh;
        float a1 = g_e[(size_t)4 * (i + 1) + h] * invh;
        uint4 v0 = *(const uint4*)(g_featb + (size_t)s0 * HID + lane * 8);
        uint4 v1 = *(const uint4*)(g_featb + (size_t)s1 * HID + lane * 8);
        float2 p;
        p = __bfloat1622float2(*(__nv_bfloat162*)&v0.x); acc[0] = fmaf(a0, p.x, acc[0]); acc[1] = fmaf(a0, p.y, acc[1]);
        p = __bfloat1622float2(*(__nv_bfloat162*)&v0.y); acc[2] = fmaf(a0, p.x, acc[2]); acc[3] = fmaf(a0, p.y, acc[3]);
        p = __bfloat1622float2(*(__nv_bfloat162*)&v0.z); acc[4] = fmaf(a0, p.x, acc[4]); acc[5] = fmaf(a0, p.y, acc[5]);
        p = __bfloat1622float2(*(__nv_bfloat162*)&v0.w); acc[6] = fmaf(a0, p.x, acc[6]); acc[7] = fmaf(a0, p.y, acc[7]);
        p = __bfloat1622float2(*(__nv_bfloat162*)&v1.x); acc[0] = fmaf(a1, p.x, acc[0]); acc[1] = fmaf(a1, p.y, acc[1]);
        p = __bfloat1622float2(*(__nv_bfloat162*)&v1.y); acc[2] = fmaf(a1, p.x, acc[2]); acc[3] = fmaf(a1, p.y, acc[3]);
        p = __bfloat1622float2(*(__nv_bfloat162*)&v1.z); acc[4] = fmaf(a1, p.x, acc[4]); acc[5] = fmaf(a1, p.y, acc[5]);
        p = __bfloat1622float2(*(__nv_bfloat162*)&v1.w); acc[6] = fmaf(a1, p.x, acc[6]); acc[7] = fmaf(a1, p.y, acc[7]);
    }
    if (i < end) {
        int s0 = g_srcs[i];
        float a0 = g_e[(size_t)4 * i + h] * invh;
        uint4 v0 = *(const uint4*)(g_featb + (size_t)s0 * HID + lane * 8);
        float2 p;
        p = __bfloat1622float2(*(__nv_bfloat162*)&v0.x); acc[0] = fmaf(a0, p.x, acc[0]); acc[1] = fmaf(a0, p.y, acc[1]);
        p = __bfloat1622float2(*(__nv_bfloat162*)&v0.y); acc[2] = fmaf(a0, p.x, acc[2]); acc[3] = fmaf(a0, p.y, acc[3]);
        p = __bfloat1622float2(*(__nv_bfloat162*)&v0.z); acc[4] = fmaf(a0, p.x, acc[4]); acc[5] = fmaf(a0, p.y, acc[5]);
        p = __bfloat1622float2(*(__nv_bfloat162*)&v0.w); acc[6] = fmaf(a0, p.x, acc[6]); acc[7] = fmaf(a0, p.y, acc[7]);
    }
#pragma unroll
    for (int j = 0; j < 8; j++) {
        float o = acc[j] + bvec[lane * 8 + j];
        out[(size_t)n * HID + lane * 8 + j] = fmaxf(o, 0.f);
    }
}

// layer 2: single head, D=256, no activation; same 2-pass structure
__global__ __launch_bounds__(256) void agg1_kernel(
    const float* __restrict__ bvec, float* __restrict__ out,
    const float* __restrict__ elp, const float* __restrict__ erp)
{
    int n = blockIdx.x * 8 + (threadIdx.x >> 5);
    if (n >= N_NODES) return;
    int lane = threadIdx.x & 31;
    int beg = g_off[n], end = g_off[n + 1];
    float ern = erp[n];

    float se = 0.f;
    for (int i = beg + lane; i < end; i += 32) {
        float ev = elp[g_srcs[i]] + ern;
        ev = (ev > 0.f) ? ev : ev * NEG;
        ev = __expf(ev);
        g_e[i] = ev;
        se += ev;
    }
#pragma unroll
    for (int o = 16; o; o >>= 1) se += __shfl_xor_sync(0xffffffffu, se, o);
    float inv = 1.f / se;
    __syncwarp();

    float acc[8];
#pragma unroll
    for (int j = 0; j < 8; j++) acc[j] = 0.f;
    int i = beg;
    for (; i + 1 < end; i += 2) {
        int s0 = g_srcs[i], s1 = g_srcs[i + 1];
        float a0 = g_e[i] * inv, a1 = g_e[i + 1] * inv;
        uint4 v0 = *(const uint4*)(g_featb + (size_t)s0 * HID + lane * 8);
        uint4 v1 = *(const uint4*)(g_featb + (size_t)s1 * HID + lane * 8);
        float2 p;
        p = __bfloat1622float2(*(__nv_bfloat162*)&v0.x); acc[0] = fmaf(a0, p.x, acc[0]); acc[1] = fmaf(a0, p.y, acc[1]);
        p = __bfloat1622float2(*(__nv_bfloat162*)&v0.y); acc[2] = fmaf(a0, p.x, acc[2]); acc[3] = fmaf(a0, p.y, acc[3]);
        p = __bfloat1622float2(*(__nv_bfloat162*)&v0.z); acc[4] = fmaf(a0, p.x, acc[4]); acc[5] = fmaf(a0, p.y, acc[5]);
        p = __bfloat1622float2(*(__nv_bfloat162*)&v0.w); acc[6] = fmaf(a0, p.x, acc[6]); acc[7] = fmaf(a0, p.y, acc[7]);
        p = __bfloat1622float2(*(__nv_bfloat162*)&v1.x); acc[0] = fmaf(a1, p.x, acc[0]); acc[1] = fmaf(a1, p.y, acc[1]);
        p = __bfloat1622float2(*(__nv_bfloat162*)&v1.y); acc[2] = fmaf(a1, p.x, acc[2]); acc[3] = fmaf(a1, p.y, acc[3]);
        p = __bfloat1622float2(*(__nv_bfloat162*)&v1.z); acc[4] = fmaf(a1, p.x, acc[4]); acc[5] = fmaf(a1, p.y, acc[5]);
        p = __bfloat1622float2(*(__nv_bfloat162*)&v1.w); acc[6] = fmaf(a1, p.x, acc[6]); acc[7] = fmaf(a1, p.y, acc[7]);
    }
    if (i < end) {
        int s0 = g_srcs[i];
        float a0 = g_e[i] * inv;
        uint4 v0 = *(const uint4*)(g_featb + (size_t)s0 * HID + lane * 8);
        float2 p;
        p = __bfloat1622float2(*(__nv_bfloat162*)&v0.x); acc[0] = fmaf(a0, p.x, acc[0]); acc[1] = fmaf(a0, p.y, acc[1]);
        p = __bfloat1622float2(*(__nv_bfloat162*)&v0.y); acc[2] = fmaf(a0, p.x, acc[2]); acc[3] = fmaf(a0, p.y, acc[3]);
        p = __bfloat1622float2(*(__nv_bfloat162*)&v0.z); acc[4] = fmaf(a0, p.x, acc[4]); acc[5] = fmaf(a0, p.y, acc[5]);
        p = __bfloat1622float2(*(__nv_bfloat162*)&v0.w); acc[6] = fmaf(a0, p.x, acc[6]); acc[7] = fmaf(a0, p.y, acc[7]);
    }
#pragma unroll
    for (int j = 0; j < 8; j++)
        out[(size_t)n * HID + lane * 8 + j] = acc[j] + bvec[lane * 8 + j];
}

// ------------------------- host launch -------------------------
extern "C" void kernel_launch(void* const* d_in, const int* in_sizes, int n_in,
                              void* d_out, int out_size)
{
    const float* feats = (const float*)d_in[0];
    const int*   src   = (const int*)d_in[1];
    const int*   dst   = (const int*)d_in[2];
    const float* W0  = (const float*)d_in[3];
    const float* al0 = (const float*)d_in[4];
    const float* ar0 = (const float*)d_in[5];
    const float* b0  = (const float*)d_in[6];
    const float* W1  = (const float*)d_in[7];
    const float* al1 = (const float*)d_in[8];
    const float* ar1 = (const float*)d_in[9];
    const float* b1  = (const float*)d_in[10];
    const float* W2  = (const float*)d_in[11];
    const float* al2 = (const float*)d_in[12];
    const float* ar2 = (const float*)d_in[13];
    const float* b2  = (const float*)d_in[14];
    float* out = (float*)d_out;

    float *p_hA, *p_hB, *p_W, *p_el, *p_er;
    __nv_bfloat16* p_featb;
    cudaGetSymbolAddress((void**)&p_featb, g_featb);
    cudaGetSymbolAddress((void**)&p_hA, g_hA);
    cudaGetSymbolAddress((void**)&p_hB, g_hB);
    cudaGetSymbolAddress((void**)&p_W, g_W);
    cudaGetSymbolAddress((void**)&p_el, g_el);
    cudaGetSymbolAddress((void**)&p_er, g_er);

    // lazily-created side stream + fork/join events (host objects only;
    // created on the uncaptured correctness call, reused under capture).
    static cudaStream_t s_side = nullptr;
    static cudaEvent_t ev_fork = nullptr, ev_join = nullptr;
    if (s_side == nullptr) {
        cudaStreamCreateWithFlags(&s_side, cudaStreamNonBlocking);
        cudaEventCreateWithFlags(&ev_fork, cudaEventDisableTiming);
        cudaEventCreateWithFlags(&ev_join, cudaEventDisableTiming);
    }

    const int SMEM_BYTES = 2 * (BM * BK + BK * BN) * 4;   // 96 KB
    cudaFuncSetAttribute(gemm_tc_kernel,
                         cudaFuncAttributeMaxDynamicSharedMemorySize, SMEM_BYTES);

    int ggrid = (N_NODES + BM - 1) / BM;   // 391 full-width tiles
    int nwN = (N_NODES + 7) / 8;
    int nzelr = (3 * ELR_STRIDE + 255) / 256;

    float* el0 = p_el;                  float* er0 = p_er;
    float* el1 = p_el + ELR_STRIDE;     float* er1 = p_er + ELR_STRIDE;
    float* el2 = p_el + 2 * ELR_STRIDE; float* er2 = p_er + 2 * ELR_STRIDE;

    // fork: CSR build runs on the side stream, overlapped with gemm0 chain.
    cudaEventRecord(ev_fork, 0);
    cudaStreamWaitEvent(s_side, ev_fork, 0);

    wround_kernel<<<(W_TOTAL + 255) / 256, 256>>>(W0, W1, W2);            // launch 0 (s0)
    zero_elr_kernel<<<nzelr, 256>>>();                                    // launch 1 (s0)
    zero_deg_kernel<<<(N_NODES + 255) / 256, 256, 0, s_side>>>();         // launch 2 (side)
    gemm_tc_kernel<<<ggrid, 512, SMEM_BYTES>>>(feats, p_W, p_featb, al0, ar0, el0, er0, N_NODES, 512, 4, 6);  // launch 3 (profiled)
    hist_kernel<<<(N_EDGES + 255) / 256, 256, 0, s_side>>>(dst);          // side
    scan_offsets_kernel<<<1, 1024, 0, s_side>>>();                        // side
    scatter_kernel<<<(N_EDGES + 255) / 256, 256, 0, s_side>>>(src, dst);  // side
    cudaEventRecord(ev_join, s_side);

    // join: agg needs CSR + gemm0 results.
    cudaStreamWaitEvent(0, ev_join, 0);
    agg4_kernel<<<nwN, 256>>>(b0, p_hA, el0, er0);

    // layer 1
    gemm_tc_kernel<<<ggrid, 512, SMEM_BYTES>>>(p_hA, p_W + W0_ELEMS, p_featb, al1, ar1, el1, er1, N_NODES, 256, 4, 6);
    agg4_kernel<<<nwN, 256>>>(b1, p_hB, el1, er1);

    // layer 2 (single head spanning all 256 cols: HL=1, hshift=8)
    gemm_tc_kernel<<<ggrid, 512, SMEM_BYTES>>>(p_hB, p_W + W0_ELEMS + W1_ELEMS, p_featb, al2, ar2, el2, er2, N_NODES, 256, 1, 8);
    agg1_kernel<<<nwN, 256>>>(b2, out, el2, er2);
}